// round 3
// baseline (speedup 1.0000x reference)
#include <cuda_runtime.h>
#include <cuda_bf16.h>
#include <cstdint>

// FSQ: q = round(4*tanh( W @ LayerNorm(x) )), folded into a single pass:
//   logit_n = rstd * (dot(x, gamma*W_n) - mu * s_n) + b_n
// R2: 2 rows/warp (regs<=85 -> 3 blocks/SM = 24 warps), LDG.128 x loads with
// prefetch pipeline, W' in smem as 16B (two K-pairs) entries read via LDS.128.

typedef unsigned long long u64;

__device__ __forceinline__ void fma2(u64 &d, u64 a, u64 b) {
    asm("fma.rn.f32x2 %0, %1, %2, %0;" : "+l"(d) : "l"(a), "l"(b));
}
__device__ __forceinline__ void add2(u64 &d, u64 a) {
    asm("add.rn.f32x2 %0, %0, %1;" : "+l"(d) : "l"(a));
}
__device__ __forceinline__ u64 pack2(float a, float b) {
    u64 r;
    asm("mov.b64 %0, {%1, %2};" : "=l"(r) : "r"(__float_as_uint(a)), "r"(__float_as_uint(b)));
    return r;
}
__device__ __forceinline__ float2 up2(u64 v) {
    unsigned a, b;
    asm("mov.b64 {%0, %1}, %2;" : "=r"(a), "=r"(b) : "l"(v));
    return make_float2(__uint_as_float(a), __uint_as_float(b));
}
__device__ __forceinline__ float pairsum(u64 v) {
    float2 f = up2(v);
    return f.x + f.y;
}

// rintf(4*tanh(x)), fast-math-proof (fmaf/rcp.rn/sqrt.rn only).
__device__ __forceinline__ float tanh4_round(float x) {
    float ax = fabsf(x);
    float r;
    if (ax >= 1.5f) {
        r = 4.0f;
    } else {
        const float T2L = 2.8853900817779268f;   // 2*log2(e)
        float t = ax * T2L;
        float k = rintf(t);
        float f = t - k;
        float y = f * 0.6931471805599453f;
        float p = 1.9841269841e-4f;
        p = fmaf(p, y, 1.3888888888e-3f);
        p = fmaf(p, y, 8.3333333333e-3f);
        p = fmaf(p, y, 4.1666666667e-2f);
        p = fmaf(p, y, 1.6666666667e-1f);
        p = fmaf(p, y, 0.5f);
        p = fmaf(p, y, 1.0f);
        p = fmaf(p, y, 1.0f);
        float scale = __int_as_float(((int)k + 127) << 23);
        float e = p * scale;                     // exp(2*ax)
        float th = (e - 1.0f) * __frcp_rn(e + 1.0f);
        r = rintf(4.0f * th);
    }
    return copysignf(r, x);
}

static const int D       = 1024;
static const int F4      = 256;   // float4 per row
static const int NL      = 8;
static const int WPAD    = 9;     // 16B entries per f4-row (8 used + 1 pad) -> 144B stride
static const int R       = 2;     // rows per warp
static const int ROWS_PB = 16;    // 8 warps * 2 rows

__global__ void __launch_bounds__(256, 3)
fsq_kernel(const float* __restrict__ x, const float* __restrict__ gamma,
           const float* __restrict__ beta, const float* __restrict__ W,
           float* __restrict__ out, int rows)
{
    // sW[i][n] : 16B = (W'[4i],W'[4i+1]) , (W'[4i+2],W'[4i+3]) for level n
    __shared__ ulonglong2 sW[F4 * WPAD];   // 36864 B
    __shared__ float sStats[ROWS_PB][12];  // per-row: sum, sumsq, 8 dots
    __shared__ float sRed[8][16];
    __shared__ float sSB[16];              // s[0..7], b[0..7]

    const int tid  = threadIdx.x;
    const int lane = tid & 31;
    const int wid  = tid >> 5;

    // ---------------- prep: W' = gamma*W into smem; s_n, b_n ----------------
    float sP[NL], bP[NL];
#pragma unroll
    for (int n = 0; n < NL; n++) { sP[n] = 0.0f; bP[n] = 0.0f; }

    {
        const float4* g4 = (const float4*)gamma;  // [256]
        const float4* e4 = (const float4*)beta;
        const float4* W4 = (const float4*)W;      // [8][256]
        int i = tid;                              // 256 threads == 256 groups
        float4 g = g4[i];
        float4 b = e4[i];
#pragma unroll
        for (int n = 0; n < NL; n++) {
            float4 w = W4[n * F4 + i];
            float p0 = g.x * w.x, p1 = g.y * w.y, p2 = g.z * w.z, p3 = g.w * w.w;
            ulonglong2 e;
            e.x = pack2(p0, p1);
            e.y = pack2(p2, p3);
            sW[i * WPAD + n] = e;
            sP[n] += (p0 + p1) + (p2 + p3);
            bP[n] += (b.x * w.x + b.y * w.y) + (b.z * w.z + b.w * w.w);
        }
    }
#pragma unroll
    for (int o = 16; o; o >>= 1) {
#pragma unroll
        for (int n = 0; n < NL; n++) {
            sP[n] += __shfl_xor_sync(0xffffffffu, sP[n], o);
            bP[n] += __shfl_xor_sync(0xffffffffu, bP[n], o);
        }
    }
    if (lane == 0) {
#pragma unroll
        for (int n = 0; n < NL; n++) {
            sRed[wid][n]     = sP[n];
            sRed[wid][8 + n] = bP[n];
        }
    }
    __syncthreads();
    if (tid < 16) {
        float v = 0.0f;
#pragma unroll
        for (int w = 0; w < 8; w++) v += sRed[w][tid];
        sSB[tid] = v;
    }
    __syncthreads();

    // ---------------- main: 2 rows per warp, single pass ----------------
    const int rowBase = blockIdx.x * ROWS_PB + wid * R;
    int r0 = rowBase,     r1 = rowBase + 1;
    if (r0 >= rows) r0 = rows - 1;
    if (r1 >= rows) r1 = rows - 1;
    const float4* xr0 = (const float4*)x + (size_t)r0 * F4;
    const float4* xr1 = (const float4*)x + (size_t)r1 * F4;

    u64 dots[R][NL];
    u64 sum2[R], ssq2[R];
#pragma unroll
    for (int r = 0; r < R; r++) {
        sum2[r] = 0ull; ssq2[r] = 0ull;
#pragma unroll
        for (int n = 0; n < NL; n++) dots[r][n] = 0ull;
    }

    float4 c0 = __ldcs(&xr0[lane]);
    float4 c1 = __ldcs(&xr1[lane]);
#pragma unroll
    for (int s = 0; s < 8; s++) {
        float4 nx0, nx1;
        if (s < 7) {
            nx0 = __ldcs(&xr0[(s + 1) * 32 + lane]);
            nx1 = __ldcs(&xr1[(s + 1) * 32 + lane]);
        }
        u64 a0 = pack2(c0.x, c0.y), b0 = pack2(c0.z, c0.w);
        u64 a1 = pack2(c1.x, c1.y), b1 = pack2(c1.z, c1.w);

        add2(sum2[0], a0); add2(sum2[0], b0);
        fma2(ssq2[0], a0, a0); fma2(ssq2[0], b0, b0);
        add2(sum2[1], a1); add2(sum2[1], b1);
        fma2(ssq2[1], a1, a1); fma2(ssq2[1], b1, b1);

        const ulonglong2* wrow = &sW[(s * 32 + lane) * WPAD];
#pragma unroll
        for (int n = 0; n < NL; n++) {
            ulonglong2 w = wrow[n];
            fma2(dots[0][n], a0, w.x); fma2(dots[0][n], b0, w.y);
            fma2(dots[1][n], a1, w.x); fma2(dots[1][n], b1, w.y);
        }
        c0 = nx0; c1 = nx1;
    }

    // ---------------- reduce + stash stats ----------------
#pragma unroll
    for (int r = 0; r < R; r++) {
        float s = pairsum(sum2[r]);
        float q = pairsum(ssq2[r]);
        float dv[NL];
#pragma unroll
        for (int n = 0; n < NL; n++) dv[n] = pairsum(dots[r][n]);
#pragma unroll
        for (int o = 16; o; o >>= 1) {
            s += __shfl_xor_sync(0xffffffffu, s, o);
            q += __shfl_xor_sync(0xffffffffu, q, o);
#pragma unroll
            for (int n = 0; n < NL; n++)
                dv[n] += __shfl_xor_sync(0xffffffffu, dv[n], o);
        }
        if (lane == 0) {
            sStats[wid * R + r][0] = s;
            sStats[wid * R + r][1] = q;
#pragma unroll
            for (int n = 0; n < NL; n++) sStats[wid * R + r][2 + n] = dv[n];
        }
    }
    __syncthreads();

    // ---------------- tail: 128 threads = 16 rows x 8 levels ----------------
    if (tid < ROWS_PB * NL) {
        int rr = tid >> 3;
        int n  = tid & 7;
        int orow = blockIdx.x * ROWS_PB + rr;
        if (orow < rows) {
            float s  = sStats[rr][0];
            float q  = sStats[rr][1];
            float dv = sStats[rr][2 + n];
            float mu   = s * (1.0f / 1024.0f);
            float var  = fmaf(-mu, mu, q * (1.0f / 1024.0f));
            float rstd = __frcp_rn(__fsqrt_rn(var + 1e-5f));
            float lg   = fmaf(rstd, fmaf(-mu, sSB[n], dv), sSB[8 + n]);
            out[(size_t)orow * NL + n] = tanh4_round(lg);
        }
    }
}

extern "C" void kernel_launch(void* const* d_in, const int* in_sizes, int n_in,
                              void* d_out, int out_size)
{
    const float* x     = (const float*)d_in[0];  // [8,8192,1024]
    const float* gamma = (const float*)d_in[1];  // [1024]
    const float* beta  = (const float*)d_in[2];  // [1024]
    const float* W     = (const float*)d_in[3];  // [8,1024]
    float* out = (float*)d_out;                  // [8,8192,8]

    int rows = in_sizes[0] / D;
    int grid = (rows + ROWS_PB - 1) / ROWS_PB;
    fsq_kernel<<<grid, 256>>>(x, gamma, beta, W, out, rows);
}

// round 4
// speedup vs baseline: 1.2502x; 1.2502x over previous
#include <cuda_runtime.h>
#include <cuda_bf16.h>
#include <cstdint>

// FSQ: q = round(4*tanh( W @ LayerNorm(x) )), folded into a single pass:
//   logit_n = rstd * (dot(x, gamma*W_n) - mu * s_n) + b_n
// R4: 4 rows/warp (W smem reads amortized 4x -> l1tex relief), scalar f32 dot
// accumulators (reg relief) + double-buffered LDG.128 row loads (DRAM latency
// cover). ssq/sum kept in f32x2. W' in smem as float4 per (f4-pos, level),
// stride 9 entries -> conflict-free LDS.128.

typedef unsigned long long u64;

__device__ __forceinline__ void fma2(u64 &d, u64 a, u64 b) {
    asm("fma.rn.f32x2 %0, %1, %2, %0;" : "+l"(d) : "l"(a), "l"(b));
}
__device__ __forceinline__ void add2(u64 &d, u64 a) {
    asm("add.rn.f32x2 %0, %0, %1;" : "+l"(d) : "l"(a));
}
__device__ __forceinline__ u64 pack2(float a, float b) {
    u64 r;
    asm("mov.b64 %0, {%1, %2};" : "=l"(r) : "r"(__float_as_uint(a)), "r"(__float_as_uint(b)));
    return r;
}
__device__ __forceinline__ float2 up2(u64 v) {
    unsigned a, b;
    asm("mov.b64 {%0, %1}, %2;" : "=r"(a), "=r"(b) : "l"(v));
    return make_float2(__uint_as_float(a), __uint_as_float(b));
}
__device__ __forceinline__ float pairsum(u64 v) {
    float2 f = up2(v);
    return f.x + f.y;
}

// rintf(4*tanh(x)), fast-math-proof (fmaf/rcp.rn/sqrt.rn only).
__device__ __forceinline__ float tanh4_round(float x) {
    float ax = fabsf(x);
    float r;
    if (ax >= 1.5f) {
        r = 4.0f;   // 4*tanh(1.5)=3.6206 -> 4; monotone beyond
    } else {
        const float T2L = 2.8853900817779268f;   // 2*log2(e)
        float t = ax * T2L;
        float k = rintf(t);
        float f = t - k;
        float y = f * 0.6931471805599453f;
        float p = 1.9841269841e-4f;
        p = fmaf(p, y, 1.3888888888e-3f);
        p = fmaf(p, y, 8.3333333333e-3f);
        p = fmaf(p, y, 4.1666666667e-2f);
        p = fmaf(p, y, 1.6666666667e-1f);
        p = fmaf(p, y, 0.5f);
        p = fmaf(p, y, 1.0f);
        p = fmaf(p, y, 1.0f);
        float scale = __int_as_float(((int)k + 127) << 23);
        float e = p * scale;                     // exp(2*ax)
        float th = (e - 1.0f) * __frcp_rn(e + 1.0f);
        r = rintf(4.0f * th);
    }
    return copysignf(r, x);
}

static const int D       = 1024;
static const int F4      = 256;   // float4 per row
static const int NL      = 8;
static const int WPAD    = 9;     // float4 entries per f4-pos (8 used + 1 pad)
static const int R       = 4;     // rows per warp
static const int ROWS_PB = 32;    // 8 warps * 4 rows

__global__ void __launch_bounds__(256, 2)
fsq_kernel(const float* __restrict__ x, const float* __restrict__ gamma,
           const float* __restrict__ beta, const float* __restrict__ W,
           float* __restrict__ out, int rows)
{
    __shared__ float4 sW[F4 * WPAD];       // 36864 B: W'[f4-pos][level]
    __shared__ float sStats[ROWS_PB][12];  // per-row: sum, sumsq, 8 dots
    __shared__ float sRed[8][16];
    __shared__ float sSB[16];              // s[0..7], b[0..7]

    const int tid  = threadIdx.x;
    const int lane = tid & 31;
    const int wid  = tid >> 5;

    // ---------------- prep: W' = gamma*W into smem; s_n, b_n ----------------
    float sP[NL], bP[NL];
#pragma unroll
    for (int n = 0; n < NL; n++) { sP[n] = 0.0f; bP[n] = 0.0f; }

    {
        const float4* g4 = (const float4*)gamma;  // [256]
        const float4* e4 = (const float4*)beta;
        const float4* W4 = (const float4*)W;      // [8][256]
        int i = tid;                              // 256 threads = 256 f4 groups
        float4 g = g4[i];
        float4 b = e4[i];
#pragma unroll
        for (int n = 0; n < NL; n++) {
            float4 w = W4[n * F4 + i];
            float4 p;
            p.x = g.x * w.x; p.y = g.y * w.y; p.z = g.z * w.z; p.w = g.w * w.w;
            sW[i * WPAD + n] = p;
            sP[n] += (p.x + p.y) + (p.z + p.w);
            bP[n] += (b.x * w.x + b.y * w.y) + (b.z * w.z + b.w * w.w);
        }
    }
#pragma unroll
    for (int o = 16; o; o >>= 1) {
#pragma unroll
        for (int n = 0; n < NL; n++) {
            sP[n] += __shfl_xor_sync(0xffffffffu, sP[n], o);
            bP[n] += __shfl_xor_sync(0xffffffffu, bP[n], o);
        }
    }
    if (lane == 0) {
#pragma unroll
        for (int n = 0; n < NL; n++) {
            sRed[wid][n]     = sP[n];
            sRed[wid][8 + n] = bP[n];
        }
    }
    __syncthreads();
    if (tid < 16) {
        float v = 0.0f;
#pragma unroll
        for (int w = 0; w < 8; w++) v += sRed[w][tid];
        sSB[tid] = v;
    }
    __syncthreads();

    // ---------------- main: 4 rows per warp, single pass ----------------
    const int rowBase = blockIdx.x * ROWS_PB + wid * R;
    const float4* xr[R];
#pragma unroll
    for (int r = 0; r < R; r++) {
        int ri = rowBase + r;
        if (ri >= rows) ri = rows - 1;
        xr[r] = (const float4*)x + (size_t)ri * F4;
    }

    float dots[R][NL];                 // scalar accumulators (32 regs)
    u64 sum2[R], ssq2[R];              // f32x2 stats
#pragma unroll
    for (int r = 0; r < R; r++) {
        sum2[r] = 0ull; ssq2[r] = 0ull;
#pragma unroll
        for (int n = 0; n < NL; n++) dots[r][n] = 0.0f;
    }

    float4 c[R];
#pragma unroll
    for (int r = 0; r < R; r++) c[r] = __ldcs(&xr[r][lane]);

#pragma unroll
    for (int s = 0; s < 8; s++) {
        float4 nx[R];
        if (s < 7) {
#pragma unroll
            for (int r = 0; r < R; r++) nx[r] = __ldcs(&xr[r][(s + 1) * 32 + lane]);
        }
        // stats (f32x2)
#pragma unroll
        for (int r = 0; r < R; r++) {
            u64 a = pack2(c[r].x, c[r].y);
            u64 b = pack2(c[r].z, c[r].w);
            add2(sum2[r], a); add2(sum2[r], b);
            fma2(ssq2[r], a, a); fma2(ssq2[r], b, b);
        }
        // dots (scalar, W read once, serves 4 rows)
        const float4* wrow = &sW[(s * 32 + lane) * WPAD];
#pragma unroll
        for (int n = 0; n < NL; n++) {
            float4 w = wrow[n];
#pragma unroll
            for (int r = 0; r < R; r++) {
                float d = dots[r][n];
                d = fmaf(c[r].x, w.x, d);
                d = fmaf(c[r].y, w.y, d);
                d = fmaf(c[r].z, w.z, d);
                d = fmaf(c[r].w, w.w, d);
                dots[r][n] = d;
            }
        }
#pragma unroll
        for (int r = 0; r < R; r++) c[r] = nx[r];
    }

    // ---------------- reduce + stash stats ----------------
#pragma unroll
    for (int r = 0; r < R; r++) {
        float s = pairsum(sum2[r]);
        float q = pairsum(ssq2[r]);
        float dv[NL];
#pragma unroll
        for (int n = 0; n < NL; n++) dv[n] = dots[r][n];
#pragma unroll
        for (int o = 16; o; o >>= 1) {
            s += __shfl_xor_sync(0xffffffffu, s, o);
            q += __shfl_xor_sync(0xffffffffu, q, o);
#pragma unroll
            for (int n = 0; n < NL; n++)
                dv[n] += __shfl_xor_sync(0xffffffffu, dv[n], o);
        }
        if (lane == 0) {
            sStats[wid * R + r][0] = s;
            sStats[wid * R + r][1] = q;
#pragma unroll
            for (int n = 0; n < NL; n++) sStats[wid * R + r][2 + n] = dv[n];
        }
    }
    __syncthreads();

    // ---------------- tail: 256 threads = 32 rows x 8 levels ----------------
    {
        int rr = tid >> 3;
        int n  = tid & 7;
        int orow = blockIdx.x * ROWS_PB + rr;
        if (orow < rows) {
            float s  = sStats[rr][0];
            float q  = sStats[rr][1];
            float dv = sStats[rr][2 + n];
            float mu   = s * (1.0f / 1024.0f);
            float var  = fmaf(-mu, mu, q * (1.0f / 1024.0f));
            float rstd = __frcp_rn(__fsqrt_rn(var + 1e-5f));
            float lg   = fmaf(rstd, fmaf(-mu, sSB[n], dv), sSB[8 + n]);
            out[(size_t)orow * NL + n] = tanh4_round(lg);
        }
    }
}

extern "C" void kernel_launch(void* const* d_in, const int* in_sizes, int n_in,
                              void* d_out, int out_size)
{
    const float* x     = (const float*)d_in[0];  // [8,8192,1024]
    const float* gamma = (const float*)d_in[1];  // [1024]
    const float* beta  = (const float*)d_in[2];  // [1024]
    const float* W     = (const float*)d_in[3];  // [8,1024]
    float* out = (float*)d_out;                  // [8,8192,8]

    int rows = in_sizes[0] / D;
    int grid = (rows + ROWS_PB - 1) / ROWS_PB;
    fsq_kernel<<<grid, 256>>>(x, gamma, beta, W, out, rows);
}